// round 16
// baseline (speedup 1.0000x reference)
#include <cuda_runtime.h>
#include <cuda_fp16.h>
#include <mma.h>
#include <math.h>

using namespace nvcuda;

#define NN   50000
#define MM   5000
#define HIDW 256
#define CCLS 40
#define EMAX   800000
#define ENHMAX 400000

// ---------------- static scratch (half features, fp32 narrow tails) -------
__device__ __align__(16) __half d_xh  [NN * 128];
__device__ __align__(16) __half d_AGGh[NN * HIDW];
__device__ __align__(16) __half d_H1h [NN * HIDW];
__device__ __align__(16) __half d_H2h [NN * HIDW];
__device__ __align__(16) __half d_G1h [NN * HIDW];
__device__ __align__(16) __half d_G2h [NN * HIDW];
__device__ __align__(16) __half d_HXTh[NN * 128];
__device__ __align__(16) __half d_XT40h [NN * CCLS];
__device__ __align__(16) __half d_HXT40h[NN * CCLS];
__device__ __align__(16) __half d_EFh [MM * HIDW];
__device__ __align__(16) __half d_EF2h[MM * HIDW];
__device__ float d_AGG40[NN * CCLS];
__device__ float d_EF40 [MM * CCLS];
__device__ float d_HYP40[NN * CCLS];
__device__ float d_SIMPLE[NN * CCLS];
// half weight pool
#define WH_S0WL 0
#define WH_S0WR 32768
#define WH_S1WL 65536
#define WH_S1WR 131072
#define WH_S2WL 196608
#define WH_S2WR 206848
#define WH_H0   217088
#define WH_H1   249856
#define WH_H2   315392
#define WH_H3   380928
#define WH_H4   446464
__device__ __align__(16) __half d_WH[456704];
// CSR structures
__device__ int d_dcnt[NN],  d_doffs[NN + 4], d_dcur[NN],  d_dlist[EMAX];
__device__ int d_necnt[MM], d_neoffs[MM + 4], d_necur[MM], d_nelist[ENHMAX];
__device__ int d_encnt[NN], d_enoffs[NN + 4], d_encur[NN], d_enlist[ENHMAX];
__device__ int d_bsumS[32], d_bsumNE[32], d_bsumEN[32];

// ---------------- fp32 -> fp16 converters ----------------
__global__ void cvt1_k(const float* __restrict__ s, __half* __restrict__ d, int n) {
    int i = blockIdx.x * blockDim.x + threadIdx.x;
    if (i < n) d[i] = __float2half_rn(s[i]);
}
struct Cvt6 { const float* s[6]; __half* d[6]; int n[6]; };
__global__ void cvtB_k(Cvt6 b) {
    int t = blockIdx.x * blockDim.x + threadIdx.x;
    int y = blockIdx.y;
    if (t < b.n[y]) b.d[y][t] = __float2half_rn(b.s[y][t]);
}

// ---------------- CSR build ----------------
__global__ void counti_k(const int* __restrict__ idx, int n, int* __restrict__ cnt) {
    int i = blockIdx.x * blockDim.x + threadIdx.x;
    if (i < n) atomicAdd(&cnt[idx[i]], 1);
}

// phase 1: per-block (1024 thr x int4 = 4096 elems) sums
__global__ void scansum_k(const int* __restrict__ cnt, int* __restrict__ bsum, int n4) {
    __shared__ int wsum[32];
    int i = blockIdx.x * 1024 + threadIdx.x;
    const int4* c4 = reinterpret_cast<const int4*>(cnt);
    int4 v = (i < n4) ? c4[i] : make_int4(0, 0, 0, 0);
    int s = v.x + v.y + v.z + v.w;
#pragma unroll
    for (int d = 16; d; d >>= 1) s += __shfl_down_sync(0xffffffffu, s, d);
    if ((threadIdx.x & 31) == 0) wsum[threadIdx.x >> 5] = s;
    __syncthreads();
    if (threadIdx.x < 32) {
        int t = wsum[threadIdx.x];
#pragma unroll
        for (int d = 16; d; d >>= 1) t += __shfl_down_sync(0xffffffffu, t, d);
        if (threadIdx.x == 0) bsum[blockIdx.x] = t;
    }
}

// phase 2: per-block local exclusive scan + serial block prefix from bsum
__global__ void scanout_k(const int* __restrict__ cnt, const int* __restrict__ bsum,
                          int* __restrict__ offs, int n) {
    __shared__ int wsum[32];
    const int n4 = n >> 2;
    const int tid = threadIdx.x, lane = tid & 31, wid = tid >> 5;
    int i = blockIdx.x * 1024 + tid;
    const int4* c4 = reinterpret_cast<const int4*>(cnt);
    int4 v = (i < n4) ? c4[i] : make_int4(0, 0, 0, 0);
    int s = v.x + v.y + v.z + v.w;
    int ps = s;
#pragma unroll
    for (int d = 1; d < 32; d <<= 1) {
        int t = __shfl_up_sync(0xffffffffu, ps, d);
        if (lane >= d) ps += t;
    }
    if (lane == 31) wsum[wid] = ps;
    __syncthreads();
    if (wid == 0) {
        int ws = wsum[lane];
#pragma unroll
        for (int d = 1; d < 32; d <<= 1) {
            int t = __shfl_up_sync(0xffffffffu, ws, d);
            if (lane >= d) ws += t;
        }
        wsum[lane] = ws;
    }
    __syncthreads();
    int pre = 0;
    for (int b = 0; b < blockIdx.x; b++) pre += bsum[b];
    int excl = pre + (wid ? wsum[wid - 1] : 0) + ps - s;
    if (i < n4) {
        int4 o;
        o.x = excl;
        o.y = excl + v.x;
        o.z = excl + v.x + v.y;
        o.w = excl + v.x + v.y + v.z;
        reinterpret_cast<int4*>(offs)[i] = o;
    }
    if (blockIdx.x == gridDim.x - 1 && tid == 0)
        offs[n] = pre + bsum[blockIdx.x];
}

__global__ void fill_k(const int* __restrict__ key, const int* __restrict__ payload,
                       int n, int* __restrict__ cursor, int* __restrict__ list) {
    int i = blockIdx.x * blockDim.x + threadIdx.x;
    if (i >= n) return;
    int pos = atomicAdd(&cursor[key[i]], 1);
    list[pos] = payload[i];
}

// ---------------- warp-tiled half gathers (hadd2-tree inner loop) --------
__global__ __launch_bounds__(256) void gather256h_k(
    const __half* __restrict__ in, const int* __restrict__ offs,
    const int* __restrict__ list, int mode, const float* __restrict__ obias,
    __half* __restrict__ out, unsigned nrows)
{
    __shared__ int sidx[8][32];
    const int wslot = threadIdx.x >> 5;
    const int lane  = threadIdx.x & 31;
    unsigned r = blockIdx.x * 8u + wslot;
    if (r >= nrows) return;

    int s = offs[r], e = offs[r + 1];
    const uint4* in4 = reinterpret_cast<const uint4*>(in);
    float acc[8];
#pragma unroll
    for (int i = 0; i < 8; i++) acc[i] = 0.f;

    auto tree4 = [&](int n0, int n1, int n2, int n3) {
        uint4 v0 = in4[(size_t)n0 * 32 + lane];
        uint4 v1 = in4[(size_t)n1 * 32 + lane];
        uint4 v2 = in4[(size_t)n2 * 32 + lane];
        uint4 v3 = in4[(size_t)n3 * 32 + lane];
        const half2* h0 = reinterpret_cast<const half2*>(&v0);
        const half2* h1 = reinterpret_cast<const half2*>(&v1);
        const half2* h2 = reinterpret_cast<const half2*>(&v2);
        const half2* h3 = reinterpret_cast<const half2*>(&v3);
#pragma unroll
        for (int p = 0; p < 4; p++) {
            half2 t = __hadd2(__hadd2(h0[p], h1[p]), __hadd2(h2[p], h3[p]));
            float2 f = __half22float2(t);
            acc[2 * p] += f.x; acc[2 * p + 1] += f.y;
        }
    };
    auto one = [&](int nb) {
        uint4 v = in4[(size_t)nb * 32 + lane];
        const half2* h = reinterpret_cast<const half2*>(&v);
#pragma unroll
        for (int p = 0; p < 4; p++) {
            float2 f = __half22float2(h[p]);
            acc[2 * p] += f.x; acc[2 * p + 1] += f.y;
        }
    };

    int base = s;
    for (; base + 32 <= e; base += 32) {
        sidx[wslot][lane] = __ldg(&list[base + lane]);
        __syncwarp();
#pragma unroll
        for (int jj = 0; jj < 32; jj += 4)
            tree4(sidx[wslot][jj], sidx[wslot][jj + 1], sidx[wslot][jj + 2], sidx[wslot][jj + 3]);
        __syncwarp();
    }
    if (base < e) {
        int cnt = e - base;
        sidx[wslot][lane] = __ldg(&list[base + min(lane, cnt - 1)]);
        __syncwarp();
        int jj = 0;
        for (; jj + 4 <= cnt; jj += 4)
            tree4(sidx[wslot][jj], sidx[wslot][jj + 1], sidx[wslot][jj + 2], sidx[wslot][jj + 3]);
        for (; jj < cnt; jj++) one(sidx[wslot][jj]);
    }

    float deg = (float)(e - s);
    float sc = (mode == 0) ? (1.0f / fmaxf(deg, 1.0f)) : (deg > 0.f ? 1.0f / deg : 0.0f);
#pragma unroll
    for (int i = 0; i < 8; i++) acc[i] *= sc;
    if (obias) {
        const float4* b4 = reinterpret_cast<const float4*>(obias);
        float4 b0 = b4[lane * 2], b1 = b4[lane * 2 + 1];
        acc[0] = fmaxf(acc[0] + b0.x, 0.f); acc[1] = fmaxf(acc[1] + b0.y, 0.f);
        acc[2] = fmaxf(acc[2] + b0.z, 0.f); acc[3] = fmaxf(acc[3] + b0.w, 0.f);
        acc[4] = fmaxf(acc[4] + b1.x, 0.f); acc[5] = fmaxf(acc[5] + b1.y, 0.f);
        acc[6] = fmaxf(acc[6] + b1.z, 0.f); acc[7] = fmaxf(acc[7] + b1.w, 0.f);
    }
    uint4 o;
    half2* oh = reinterpret_cast<half2*>(&o);
#pragma unroll
    for (int p = 0; p < 4; p++) oh[p] = __floats2half2_rn(acc[2 * p], acc[2 * p + 1]);
    reinterpret_cast<uint4*>(out)[(size_t)r * 32 + lane] = o;
}

__global__ __launch_bounds__(256) void gather128h_k(
    const __half* __restrict__ in, const int* __restrict__ offs,
    const int* __restrict__ list, int mode,
    __half* __restrict__ out, unsigned nrows)
{
    __shared__ int sidx[8][32];
    const int wslot = threadIdx.x >> 5;
    const int lane  = threadIdx.x & 31;
    unsigned r = blockIdx.x * 8u + wslot;
    if (r >= nrows) return;

    int s = offs[r], e = offs[r + 1];
    const uint2* in2 = reinterpret_cast<const uint2*>(in);
    float acc[4] = {0.f, 0.f, 0.f, 0.f};

    auto tree4 = [&](int n0, int n1, int n2, int n3) {
        uint2 v0 = in2[(size_t)n0 * 32 + lane];
        uint2 v1 = in2[(size_t)n1 * 32 + lane];
        uint2 v2 = in2[(size_t)n2 * 32 + lane];
        uint2 v3 = in2[(size_t)n3 * 32 + lane];
        const half2* h0 = reinterpret_cast<const half2*>(&v0);
        const half2* h1 = reinterpret_cast<const half2*>(&v1);
        const half2* h2 = reinterpret_cast<const half2*>(&v2);
        const half2* h3 = reinterpret_cast<const half2*>(&v3);
#pragma unroll
        for (int p = 0; p < 2; p++) {
            half2 t = __hadd2(__hadd2(h0[p], h1[p]), __hadd2(h2[p], h3[p]));
            float2 f = __half22float2(t);
            acc[2 * p] += f.x; acc[2 * p + 1] += f.y;
        }
    };
    auto one = [&](int nb) {
        uint2 v = in2[(size_t)nb * 32 + lane];
        const half2* h = reinterpret_cast<const half2*>(&v);
        float2 f0 = __half22float2(h[0]), f1 = __half22float2(h[1]);
        acc[0] += f0.x; acc[1] += f0.y; acc[2] += f1.x; acc[3] += f1.y;
    };

    int base = s;
    for (; base + 32 <= e; base += 32) {
        sidx[wslot][lane] = __ldg(&list[base + lane]);
        __syncwarp();
#pragma unroll
        for (int jj = 0; jj < 32; jj += 4)
            tree4(sidx[wslot][jj], sidx[wslot][jj + 1], sidx[wslot][jj + 2], sidx[wslot][jj + 3]);
        __syncwarp();
    }
    if (base < e) {
        int cnt = e - base;
        sidx[wslot][lane] = __ldg(&list[base + min(lane, cnt - 1)]);
        __syncwarp();
        int jj = 0;
        for (; jj + 4 <= cnt; jj += 4)
            tree4(sidx[wslot][jj], sidx[wslot][jj + 1], sidx[wslot][jj + 2], sidx[wslot][jj + 3]);
        for (; jj < cnt; jj++) one(sidx[wslot][jj]);
    }

    float deg = (float)(e - s);
    float sc = (mode == 0) ? (1.0f / fmaxf(deg, 1.0f)) : (deg > 0.f ? 1.0f / deg : 0.0f);
    uint2 o;
    half2* oh = reinterpret_cast<half2*>(&o);
    oh[0] = __floats2half2_rn(acc[0] * sc, acc[1] * sc);
    oh[1] = __floats2half2_rn(acc[2] * sc, acc[3] * sc);
    reinterpret_cast<uint2*>(out)[(size_t)r * 32 + lane] = o;
}

// 40-wide half-in -> fp32-out, hadd2 pair tree. thread = (row, chunk of 8).
__global__ void gather40h_k(const __half* __restrict__ in, const int* __restrict__ offs,
                            const int* __restrict__ list, int mode,
                            float* __restrict__ out, unsigned nrows) {
    unsigned t = blockIdx.x * blockDim.x + threadIdx.x;
    if (t >= nrows * 5) return;
    unsigned r = t / 5;
    unsigned c = t - r * 5;
    int s = offs[r], e = offs[r + 1];
    const uint4* in4 = reinterpret_cast<const uint4*>(in);
    float acc[8];
#pragma unroll
    for (int i = 0; i < 8; i++) acc[i] = 0.f;
    int j = s;
    for (; j + 2 <= e; j += 2) {
        int n0 = __ldg(&list[j]), n1 = __ldg(&list[j + 1]);
        uint4 v0 = in4[(size_t)n0 * 5 + c];
        uint4 v1 = in4[(size_t)n1 * 5 + c];
        const half2* h0 = reinterpret_cast<const half2*>(&v0);
        const half2* h1 = reinterpret_cast<const half2*>(&v1);
#pragma unroll
        for (int p = 0; p < 4; p++) {
            float2 f = __half22float2(__hadd2(h0[p], h1[p]));
            acc[2 * p] += f.x; acc[2 * p + 1] += f.y;
        }
    }
    for (; j < e; j++) {
        int nb = __ldg(&list[j]);
        uint4 v = in4[(size_t)nb * 5 + c];
        const half2* h = reinterpret_cast<const half2*>(&v);
#pragma unroll
        for (int p = 0; p < 4; p++) {
            float2 f = __half22float2(h[p]);
            acc[2 * p] += f.x; acc[2 * p + 1] += f.y;
        }
    }
    float deg = (float)(e - s);
    float sc = (mode == 0) ? (1.0f / fmaxf(deg, 1.0f)) : (deg > 0.f ? 1.0f / deg : 0.0f);
    float4* o4 = reinterpret_cast<float4*>(out);
    o4[(size_t)r * 10 + c * 2 + 0] = make_float4(acc[0] * sc, acc[1] * sc, acc[2] * sc, acc[3] * sc);
    o4[(size_t)r * 10 + c * 2 + 1] = make_float4(acc[4] * sc, acc[5] * sc, acc[6] * sc, acc[7] * sc);
}

// 40-wide fp32-in -> fp32-out (runtime F4 = 10)
__global__ void gather_small_k(const float* __restrict__ in, const int* __restrict__ offs,
                               const int* __restrict__ list, int mode,
                               float* __restrict__ out, unsigned nrows, unsigned F4) {
    unsigned t = blockIdx.x * blockDim.x + threadIdx.x;
    if (t >= nrows * F4) return;
    unsigned r = t / F4;
    unsigned f4 = t - r * F4;
    int s = offs[r], e = offs[r + 1];
    const float4* in4 = reinterpret_cast<const float4*>(in);
    float4 acc = make_float4(0.f, 0.f, 0.f, 0.f);
    int j = s;
    for (; j + 4 <= e; j += 4) {
        int n0 = __ldg(&list[j]), n1 = __ldg(&list[j + 1]);
        int n2 = __ldg(&list[j + 2]), n3 = __ldg(&list[j + 3]);
        float4 v0 = in4[(size_t)n0 * F4 + f4];
        float4 v1 = in4[(size_t)n1 * F4 + f4];
        float4 v2 = in4[(size_t)n2 * F4 + f4];
        float4 v3 = in4[(size_t)n3 * F4 + f4];
        acc.x += v0.x + v1.x + v2.x + v3.x;
        acc.y += v0.y + v1.y + v2.y + v3.y;
        acc.z += v0.z + v1.z + v2.z + v3.z;
        acc.w += v0.w + v1.w + v2.w + v3.w;
    }
    for (; j < e; j++) {
        int nb = __ldg(&list[j]);
        float4 v = in4[(size_t)nb * F4 + f4];
        acc.x += v.x; acc.y += v.y; acc.z += v.z; acc.w += v.w;
    }
    float deg = (float)(e - s);
    float sc = (mode == 0) ? (1.0f / fmaxf(deg, 1.0f)) : (deg > 0.f ? 1.0f / deg : 0.0f);
    reinterpret_cast<float4*>(out)[t] = make_float4(acc.x * sc, acc.y * sc, acc.z * sc, acc.w * sc);
}

// ---------------- fp16 tensor-core dual GEMM (fp32 accumulate) ----------
#define BN 64
#define BKH 64
#define LDKH 72
#define CLD 36

template <int BMT>
__global__ __launch_bounds__(256, 2) void gemm_h_k(
    const __half* __restrict__ A1, const __half* __restrict__ W1,
    const __half* __restrict__ A2, const __half* __restrict__ W2,
    const float* __restrict__ addin, const float* __restrict__ bias,
    void* __restrict__ Cp, int Nr, int K, int O, int relu, int outHalf)
{
    constexpr int MI = BMT / 64;
    __shared__ union {
        struct {
            __half As[2][BMT][LDKH];
            __half Bs[2][BN][LDKH];
        } t;
        float Cs[8][16 * MI * CLD];
    } sm;

    const int bm   = blockIdx.y * BMT;
    const int bn   = blockIdx.x * BN;
    const int tid  = threadIdx.x;
    const int wid  = tid >> 5;
    const int lane = tid & 31;
    const int warpM = (wid >> 1) * (BMT / 4);
    const int warpN = (wid & 1) * 32;

    const int KT = K / BKH;
    const int npass = A2 ? 2 : 1;
    const int T = KT * npass;

    auto issue = [&](int t, int buf) {
        int p  = t / KT;
        int k0 = (t - p * KT) * BKH;
        const __half* A = p ? A2 : A1;
        const __half* W = p ? W2 : W1;
#pragma unroll
        for (int l = 0; l < BMT / 32; l++) {
            int e = tid + l * 256;
            int row = e >> 3, c8 = e & 7;
            int gm = min(bm + row, Nr - 1);
            const __half* src = A + (size_t)gm * K + k0 + c8 * 8;
            unsigned dst = (unsigned)__cvta_generic_to_shared(&sm.t.As[buf][row][c8 * 8]);
            asm volatile("cp.async.cg.shared.global [%0], [%1], 16;" :: "r"(dst), "l"(src));
        }
#pragma unroll
        for (int l = 0; l < 2; l++) {
            int e = tid + l * 256;
            int row = e >> 3, c8 = e & 7;
            int gn = min(bn + row, O - 1);
            const __half* src = W + (size_t)gn * K + k0 + c8 * 8;
            unsigned dst = (unsigned)__cvta_generic_to_shared(&sm.t.Bs[buf][row][c8 * 8]);
            asm volatile("cp.async.cg.shared.global [%0], [%1], 16;" :: "r"(dst), "l"(src));
        }
        asm volatile("cp.async.commit_group;");
    };

    wmma::fragment<wmma::accumulator, 16, 16, 16, float> acc[MI][2];
#pragma unroll
    for (int i = 0; i < MI; i++)
#pragma unroll
        for (int j = 0; j < 2; j++) wmma::fill_fragment(acc[i][j], 0.0f);

    issue(0, 0);
    for (int t = 0; t < T; t++) {
        int buf = t & 1;
        if (t + 1 < T) {
            issue(t + 1, buf ^ 1);
            asm volatile("cp.async.wait_group 1;");
        } else {
            asm volatile("cp.async.wait_group 0;");
        }
        __syncthreads();

#pragma unroll
        for (int kk = 0; kk < BKH; kk += 16) {
            wmma::fragment<wmma::matrix_a, 16, 16, 16, __half, wmma::row_major> af[MI];
            wmma::fragment<wmma::matrix_b, 16, 16, 16, __half, wmma::col_major> bf[2];
#pragma unroll
            for (int i = 0; i < MI; i++)
                wmma::load_matrix_sync(af[i], &sm.t.As[buf][warpM + i * 16][kk], LDKH);
#pragma unroll
            for (int j = 0; j < 2; j++)
                wmma::load_matrix_sync(bf[j], &sm.t.Bs[buf][warpN + j * 16][kk], LDKH);
#pragma unroll
            for (int i = 0; i < MI; i++)
#pragma unroll
                for (int j = 0; j < 2; j++)
                    wmma::mma_sync(acc[i][j], af[i], bf[j], acc[i][j]);
        }
        __syncthreads();
    }

#pragma unroll
    for (int i = 0; i < MI; i++)
#pragma unroll
        for (int j = 0; j < 2; j++)
            wmma::store_matrix_sync(&sm.Cs[wid][(i * 16) * CLD + j * 16], acc[i][j],
                                    CLD, wmma::mem_row_major);
    __syncwarp();

    for (int idx = lane; idx < 16 * MI * 32; idx += 32) {
        int r = idx >> 5;
        int c = idx & 31;
        int m = bm + warpM + r;
        int n = bn + warpN + c;
        if (m >= Nr || n >= O) continue;
        float v = sm.Cs[wid][r * CLD + c];
        if (addin) v += addin[(size_t)m * O + n];
        if (bias)  v += bias[n];
        if (relu)  v = fmaxf(v, 0.0f);
        if (outHalf) ((__half*)Cp)[(size_t)m * O + n] = __float2half_rn(v);
        else         ((float*)Cp)[(size_t)m * O + n] = v;
    }
}

// ---------------- final: logits + log_softmax (hb added to Hy) ----------------
__global__ void final_k(const float* __restrict__ S, const float* __restrict__ Hy,
                        const float* __restrict__ hb,
                        const float* __restrict__ lpw, const float* __restrict__ lpb,
                        float* __restrict__ out, int n) {
    __shared__ float w[CCLS * 2 * CCLS];
    __shared__ float bb[CCLS];
    __shared__ float hbb[CCLS];
    for (int i = threadIdx.x; i < CCLS * 2 * CCLS; i += blockDim.x) w[i] = lpw[i];
    for (int i = threadIdx.x; i < CCLS; i += blockDim.x) { bb[i] = lpb[i]; hbb[i] = hb[i]; }
    __syncthreads();
    int node = blockIdx.x * blockDim.x + threadIdx.x;
    if (node >= n) return;

    float sv[CCLS], hv[CCLS];
#pragma unroll
    for (int k = 0; k < CCLS; k++) {
        sv[k] = S [node * CCLS + k];
        hv[k] = Hy[node * CCLS + k] + hbb[k];
    }
    float logits[CCLS];
#pragma unroll 4
    for (int c = 0; c < CCLS; c++) {
        float acc = bb[c];
        const float* wr = &w[c * 2 * CCLS];
#pragma unroll
        for (int k = 0; k < CCLS; k++) acc += sv[k] * wr[k];
#pragma unroll
        for (int k = 0; k < CCLS; k++) acc += hv[k] * wr[CCLS + k];
        logits[c] = acc;
    }
    float mx = -1e30f;
#pragma unroll
    for (int c = 0; c < CCLS; c++) mx = fmaxf(mx, logits[c]);
    float sum = 0.0f;
#pragma unroll
    for (int c = 0; c < CCLS; c++) sum += __expf(logits[c] - mx);
    float lse = mx + logf(sum);
#pragma unroll
    for (int c = 0; c < CCLS; c++) out[node * CCLS + c] = logits[c] - lse;
}

// =======================================================================
extern "C" void kernel_launch(void* const* d_in, const int* in_sizes, int n_in,
                              void* d_out, int out_size) {
    const float* x       = (const float*)d_in[0];
    const int*   src     = (const int*)  d_in[1];
    const int*   dst     = (const int*)  d_in[2];
    const int*   he_node = (const int*)  d_in[3];
    const int*   he_edge = (const int*)  d_in[4];
    const float* s0wl = (const float*)d_in[5],  *s0wr = (const float*)d_in[6],  *s0b = (const float*)d_in[7];
    const float* s1wl = (const float*)d_in[8],  *s1wr = (const float*)d_in[9],  *s1b = (const float*)d_in[10];
    const float* s2wl = (const float*)d_in[11], *s2wr = (const float*)d_in[12], *s2b = (const float*)d_in[13];
    const float* h0w = (const float*)d_in[14], *h0b = (const float*)d_in[15];
    const float* h1w = (const float*)d_in[16], *h1b = (const float*)d_in[17];
    const float* h2w = (const float*)d_in[18], *h2b = (const float*)d_in[19];
    const float* h3w = (const float*)d_in[20], *h3b = (const float*)d_in[21];
    const float* h4w = (const float*)d_in[22], *h4b = (const float*)d_in[23];
    const float* lpw = (const float*)d_in[24], *lpb = (const float*)d_in[25];

    const int E   = in_sizes[1];
    const int ENH = in_sizes[3];
    const int FIN = in_sizes[0] / NN;   // 128

    __half *xh, *AGGh, *H1h, *H2h, *G1h, *G2h, *HXTh, *XT40h, *HXT40h, *EFh, *EF2h, *WH;
    float *AGG40, *EF40, *HYP40, *SIMPLE;
    cudaGetSymbolAddress((void**)&xh,     d_xh);
    cudaGetSymbolAddress((void**)&AGGh,   d_AGGh);
    cudaGetSymbolAddress((void**)&H1h,    d_H1h);
    cudaGetSymbolAddress((void**)&H2h,    d_H2h);
    cudaGetSymbolAddress((void**)&G1h,    d_G1h);
    cudaGetSymbolAddress((void**)&G2h,    d_G2h);
    cudaGetSymbolAddress((void**)&HXTh,   d_HXTh);
    cudaGetSymbolAddress((void**)&XT40h,  d_XT40h);
    cudaGetSymbolAddress((void**)&HXT40h, d_HXT40h);
    cudaGetSymbolAddress((void**)&EFh,    d_EFh);
    cudaGetSymbolAddress((void**)&EF2h,   d_EF2h);
    cudaGetSymbolAddress((void**)&WH,     d_WH);
    cudaGetSymbolAddress((void**)&AGG40,  d_AGG40);
    cudaGetSymbolAddress((void**)&EF40,   d_EF40);
    cudaGetSymbolAddress((void**)&HYP40,  d_HYP40);
    cudaGetSymbolAddress((void**)&SIMPLE, d_SIMPLE);

    int *dcnt, *doffs, *dcur, *dlist;
    int *necnt, *neoffs, *necur, *nelist;
    int *encnt, *enoffs, *encur, *enlist;
    int *bsumS, *bsumNE, *bsumEN;
    cudaGetSymbolAddress((void**)&dcnt,  d_dcnt);
    cudaGetSymbolAddress((void**)&doffs, d_doffs);
    cudaGetSymbolAddress((void**)&dcur,  d_dcur);
    cudaGetSymbolAddress((void**)&dlist, d_dlist);
    cudaGetSymbolAddress((void**)&necnt,  d_necnt);
    cudaGetSymbolAddress((void**)&neoffs, d_neoffs);
    cudaGetSymbolAddress((void**)&necur,  d_necur);
    cudaGetSymbolAddress((void**)&nelist, d_nelist);
    cudaGetSymbolAddress((void**)&encnt,  d_encnt);
    cudaGetSymbolAddress((void**)&enoffs, d_enoffs);
    cudaGetSymbolAddress((void**)&encur,  d_encur);
    cudaGetSymbolAddress((void**)&enlist, d_enlist);
    cudaGetSymbolAddress((void**)&bsumS,  d_bsumS);
    cudaGetSymbolAddress((void**)&bsumNE, d_bsumNE);
    cudaGetSymbolAddress((void**)&bsumEN, d_bsumEN);

    const int TB = 256;
    auto cdiv = [](int a, int b) { return (a + b - 1) / b; };
    dim3 gemm_blk(256);
    auto grid128 = [&](int Nr, int O) {
        return dim3((unsigned)cdiv(O, BN), (unsigned)cdiv(Nr, 128));
    };
    auto grid64 = [&](int Nr, int O) {
        return dim3((unsigned)cdiv(O, BN), (unsigned)cdiv(Nr, 64));
    };
    const int SB_NN = cdiv(NN / 4, 1024);
    const int SB_MM = cdiv(MM / 4, 1024);

    // -------- streams/events: created once, reused (R14 leak lesson) --------
    static cudaStream_t hs = nullptr, hs2 = nullptr, hs3 = nullptr;
    static cudaEvent_t evFork = nullptr, evXh = nullptr, evD = nullptr,
                       evEn = nullptr, evJoin = nullptr;
    if (!hs) {
        cudaStreamCreateWithFlags(&hs,  cudaStreamNonBlocking);
        cudaStreamCreateWithFlags(&hs2, cudaStreamNonBlocking);
        cudaStreamCreateWithFlags(&hs3, cudaStreamNonBlocking);
        cudaEventCreateWithFlags(&evFork, cudaEventDisableTiming);
        cudaEventCreateWithFlags(&evXh,   cudaEventDisableTiming);
        cudaEventCreateWithFlags(&evD,    cudaEventDisableTiming);
        cudaEventCreateWithFlags(&evEn,   cudaEventDisableTiming);
        cudaEventCreateWithFlags(&evJoin, cudaEventDisableTiming);
    }

    // -------- fork immediately: CSR builds overlap the conversions --------
    cudaEventRecord(evFork, 0);
    cudaStreamWaitEvent(hs,  evFork, 0);
    cudaStreamWaitEvent(hs2, evFork, 0);
    cudaStreamWaitEvent(hs3, evFork, 0);

    // ======== stream hs2: d-CSR build (SAGE) ========
    cudaMemsetAsync(dcnt, 0, NN * sizeof(int), hs2);
    counti_k<<<cdiv(E, TB), TB, 0, hs2>>>(dst, E, dcnt);
    scansum_k<<<SB_NN, 1024, 0, hs2>>>(dcnt, bsumS, NN / 4);
    scanout_k<<<SB_NN, 1024, 0, hs2>>>(dcnt, bsumS, doffs, NN);
    cudaMemcpyAsync(dcur, doffs, NN * sizeof(int), cudaMemcpyDeviceToDevice, hs2);
    fill_k<<<cdiv(E, TB), TB, 0, hs2>>>(dst, src, E, dcur, dlist);
    cudaEventRecord(evD, hs2);

    // ======== stream hs3: en-CSR build (hyper node side) ========
    cudaMemsetAsync(encnt, 0, NN * sizeof(int), hs3);
    counti_k<<<cdiv(ENH, TB), TB, 0, hs3>>>(he_node, ENH, encnt);
    scansum_k<<<SB_NN, 1024, 0, hs3>>>(encnt, bsumEN, NN / 4);
    scanout_k<<<SB_NN, 1024, 0, hs3>>>(encnt, bsumEN, enoffs, NN);
    cudaMemcpyAsync(encur, enoffs, NN * sizeof(int), cudaMemcpyDeviceToDevice, hs3);
    fill_k<<<cdiv(ENH, TB), TB, 0, hs3>>>(he_node, he_edge, ENH, encur, enlist);
    cudaEventRecord(evEn, hs3);

    // ======== stream 0: conversions, then SAGE chain ========
    cvt1_k<<<cdiv(NN * FIN, TB), TB, 0, 0>>>(x, xh, NN * FIN);
    cudaEventRecord(evXh, 0);
    {
        Cvt6 b;
        b.s[0] = s0wl; b.d[0] = WH + WH_S0WL; b.n[0] = HIDW * FIN;
        b.s[1] = s0wr; b.d[1] = WH + WH_S0WR; b.n[1] = HIDW * FIN;
        b.s[2] = s1wl; b.d[2] = WH + WH_S1WL; b.n[2] = HIDW * HIDW;
        b.s[3] = s1wr; b.d[3] = WH + WH_S1WR; b.n[3] = HIDW * HIDW;
        b.s[4] = s2wl; b.d[4] = WH + WH_S2WL; b.n[4] = CCLS * HIDW;
        b.s[5] = s2wr; b.d[5] = WH + WH_S2WR; b.n[5] = CCLS * HIDW;
        cvtB_k<<<dim3(cdiv(HIDW * HIDW, TB), 6), TB, 0, 0>>>(b);
    }
    cudaStreamWaitEvent(0, evD, 0);   // d-CSR ready (joins hs2)

    gather128h_k<<<cdiv(NN, 8), 256, 0, 0>>>(xh, doffs, dlist, 0, AGGh, NN);
    gemm_h_k<128><<<grid128(NN, HIDW), gemm_blk, 0, 0>>>(AGGh, WH + WH_S0WL, xh, WH + WH_S0WR,
                                                         nullptr, s0b, H1h, NN, FIN, HIDW, 1, 1);
    gather256h_k<<<cdiv(NN, 8), 256, 0, 0>>>(H1h, doffs, dlist, 0, nullptr, AGGh, NN);
    gemm_h_k<128><<<grid128(NN, HIDW), gemm_blk, 0, 0>>>(AGGh, WH + WH_S1WL, H1h, WH + WH_S1WR,
                                                         nullptr, s1b, H2h, NN, HIDW, HIDW, 1, 1);
    gemm_h_k<128><<<grid128(NN, CCLS), gemm_blk, 0, 0>>>(H2h, WH + WH_S2WL, nullptr, nullptr,
                                                         nullptr, nullptr, XT40h, NN, HIDW, CCLS, 0, 1);
    gather40h_k<<<cdiv(NN * 5, TB), TB, 0, 0>>>(XT40h, doffs, dlist, 0, AGG40, NN);
    gemm_h_k<128><<<grid128(NN, CCLS), gemm_blk, 0, 0>>>(H2h, WH + WH_S2WR, nullptr, nullptr,
                                                         AGG40, s2b, SIMPLE, NN, HIDW, CCLS, 0, 0);

    // ======== stream hs: hyper weights + ne-CSR + hyper chain ========
    {
        Cvt6 b;
        b.s[0] = h0w; b.d[0] = WH + WH_H0; b.n[0] = HIDW * FIN;
        b.s[1] = h1w; b.d[1] = WH + WH_H1; b.n[1] = HIDW * HIDW;
        b.s[2] = h2w; b.d[2] = WH + WH_H2; b.n[2] = HIDW * HIDW;
        b.s[3] = h3w; b.d[3] = WH + WH_H3; b.n[3] = HIDW * HIDW;
        b.s[4] = h4w; b.d[4] = WH + WH_H4; b.n[4] = CCLS * HIDW;
        b.s[5] = h4w; b.d[5] = WH + WH_H4; b.n[5] = 0;
        cvtB_k<<<dim3(cdiv(HIDW * HIDW, TB), 6), TB, 0, hs>>>(b);
    }
    cudaMemsetAsync(necnt, 0, MM * sizeof(int), hs);
    counti_k<<<cdiv(ENH, TB), TB, 0, hs>>>(he_edge, ENH, necnt);
    scansum_k<<<SB_MM, 1024, 0, hs>>>(necnt, bsumNE, MM / 4);
    scanout_k<<<SB_MM, 1024, 0, hs>>>(necnt, bsumNE, neoffs, MM);
    cudaMemcpyAsync(necur, neoffs, MM * sizeof(int), cudaMemcpyDeviceToDevice, hs);
    fill_k<<<cdiv(ENH, TB), TB, 0, hs>>>(he_edge, he_node, ENH, necur, nelist);

    cudaStreamWaitEvent(hs, evXh, 0);   // xh ready
    gather128h_k<<<cdiv(MM, 8), 256, 0, hs>>>(xh, neoffs, nelist, 1, EFh, MM);
    cudaStreamWaitEvent(hs, evEn, 0);   // en-CSR ready (joins hs3)
    gather128h_k<<<cdiv(NN, 8), 256, 0, hs>>>(EFh, enoffs, enlist, 1, HXTh, NN);
    gemm_h_k<128><<<grid128(NN, HIDW), gemm_blk, 0, hs>>>(HXTh, WH + WH_H0, nullptr, nullptr,
                                                          nullptr, h0b, G1h, NN, FIN, HIDW, 1, 1);

    auto hyper_mid = [&](const __half* gin, const __half* w, const float* ob, __half* gout) {
        gather256h_k<<<cdiv(MM, 8), 256, 0, hs>>>(gin, neoffs, nelist, 1, nullptr, EFh, MM);
        gemm_h_k<64><<<grid64(MM, HIDW), gemm_blk, 0, hs>>>(EFh, w, nullptr, nullptr,
                                                            nullptr, nullptr, EF2h, MM, HIDW, HIDW, 0, 1);
        gather256h_k<<<cdiv(NN, 8), 256, 0, hs>>>(EF2h, enoffs, enlist, 1, ob, gout, NN);
    };
    hyper_mid(G1h, WH + WH_H1, h1b, G2h);
    hyper_mid(G2h, WH + WH_H2, h2b, G1h);
    hyper_mid(G1h, WH + WH_H3, h3b, G2h);

    gemm_h_k<128><<<grid128(NN, CCLS), gemm_blk, 0, hs>>>(G2h, WH + WH_H4, nullptr, nullptr,
                                                          nullptr, nullptr, HXT40h, NN, HIDW, CCLS, 0, 1);
    gather40h_k<<<cdiv(MM * 5, TB), TB, 0, hs>>>(HXT40h, neoffs, nelist, 1, EF40, MM);
    gather_small_k<<<cdiv(NN * 10, TB), TB, 0, hs>>>(EF40, enoffs, enlist, 1, HYP40, NN, 10);

    // -------- join + final --------
    cudaEventRecord(evJoin, hs);
    cudaStreamWaitEvent(0, evJoin, 0);
    final_k<<<cdiv(NN, 128), 128, 0, 0>>>(SIMPLE, HYP40, h4b, lpw, lpb, (float*)d_out, NN);
}

// round 17
// speedup vs baseline: 1.4199x; 1.4199x over previous
#include <cuda_runtime.h>
#include <cuda_fp16.h>
#include <mma.h>
#include <math.h>

using namespace nvcuda;

#define NN   50000
#define MM   5000
#define HIDW 256
#define CCLS 40
#define EMAX   800000
#define ENHMAX 400000

// ---------------- static scratch (half features, fp32 narrow tails) -------
__device__ __align__(16) __half d_xh  [NN * 128];
__device__ __align__(16) __half d_AGGh[NN * HIDW];
__device__ __align__(16) __half d_H1h [NN * HIDW];
__device__ __align__(16) __half d_H2h [NN * HIDW];
__device__ __align__(16) __half d_G1h [NN * HIDW];
__device__ __align__(16) __half d_G2h [NN * HIDW];
__device__ __align__(16) __half d_HXTh[NN * 128];
__device__ __align__(16) __half d_XT40h [NN * CCLS];
__device__ __align__(16) __half d_HXT40h[NN * CCLS];
__device__ __align__(16) __half d_EFh [MM * HIDW];
__device__ __align__(16) __half d_EF2h[MM * HIDW];
__device__ float d_AGG40[NN * CCLS];
__device__ float d_EF40 [MM * CCLS];
__device__ float d_HYP40[NN * CCLS];
__device__ float d_SIMPLE[NN * CCLS];
// half weight pool
#define WH_S0WL 0
#define WH_S0WR 32768
#define WH_S1WL 65536
#define WH_S1WR 131072
#define WH_S2WL 196608
#define WH_S2WR 206848
#define WH_H0   217088
#define WH_H1   249856
#define WH_H2   315392
#define WH_H3   380928
#define WH_H4   446464
__device__ __align__(16) __half d_WH[456704];
// CSR structures
__device__ int d_dcnt[NN],  d_doffs[NN + 4], d_dcur[NN],  d_dlist[EMAX];
__device__ int d_necnt[MM], d_neoffs[MM + 4], d_necur[MM], d_nelist[ENHMAX];
__device__ int d_encnt[NN], d_enoffs[NN + 4], d_encur[NN], d_enlist[ENHMAX];
__device__ int d_bsumS[32], d_bsumNE[32], d_bsumEN[32];

// ---------------- fp32 -> fp16 converters ----------------
__global__ void cvt1_k(const float* __restrict__ s, __half* __restrict__ d, int n) {
    int i = blockIdx.x * blockDim.x + threadIdx.x;
    if (i < n) d[i] = __float2half_rn(s[i]);
}
struct Cvt6 { const float* s[6]; __half* d[6]; int n[6]; };
__global__ void cvtB_k(Cvt6 b) {
    int t = blockIdx.x * blockDim.x + threadIdx.x;
    int y = blockIdx.y;
    if (t < b.n[y]) b.d[y][t] = __float2half_rn(b.s[y][t]);
}

// ---------------- CSR build ----------------
__global__ void counti_k(const int* __restrict__ idx, int n, int* __restrict__ cnt) {
    int i = blockIdx.x * blockDim.x + threadIdx.x;
    if (i < n) atomicAdd(&cnt[idx[i]], 1);
}

// phase 1: per-block (1024 thr x int4 = 4096 elems) sums
__global__ void scansum_k(const int* __restrict__ cnt, int* __restrict__ bsum, int n4) {
    __shared__ int wsum[32];
    int i = blockIdx.x * 1024 + threadIdx.x;
    const int4* c4 = reinterpret_cast<const int4*>(cnt);
    int4 v = (i < n4) ? c4[i] : make_int4(0, 0, 0, 0);
    int s = v.x + v.y + v.z + v.w;
#pragma unroll
    for (int d = 16; d; d >>= 1) s += __shfl_down_sync(0xffffffffu, s, d);
    if ((threadIdx.x & 31) == 0) wsum[threadIdx.x >> 5] = s;
    __syncthreads();
    if (threadIdx.x < 32) {
        int t = wsum[threadIdx.x];
#pragma unroll
        for (int d = 16; d; d >>= 1) t += __shfl_down_sync(0xffffffffu, t, d);
        if (threadIdx.x == 0) bsum[blockIdx.x] = t;
    }
}

// phase 2: per-block local exclusive scan + serial block prefix from bsum
__global__ void scanout_k(const int* __restrict__ cnt, const int* __restrict__ bsum,
                          int* __restrict__ offs, int n) {
    __shared__ int wsum[32];
    const int n4 = n >> 2;
    const int tid = threadIdx.x, lane = tid & 31, wid = tid >> 5;
    int i = blockIdx.x * 1024 + tid;
    const int4* c4 = reinterpret_cast<const int4*>(cnt);
    int4 v = (i < n4) ? c4[i] : make_int4(0, 0, 0, 0);
    int s = v.x + v.y + v.z + v.w;
    int ps = s;
#pragma unroll
    for (int d = 1; d < 32; d <<= 1) {
        int t = __shfl_up_sync(0xffffffffu, ps, d);
        if (lane >= d) ps += t;
    }
    if (lane == 31) wsum[wid] = ps;
    __syncthreads();
    if (wid == 0) {
        int ws = wsum[lane];
#pragma unroll
        for (int d = 1; d < 32; d <<= 1) {
            int t = __shfl_up_sync(0xffffffffu, ws, d);
            if (lane >= d) ws += t;
        }
        wsum[lane] = ws;
    }
    __syncthreads();
    int pre = 0;
    for (int b = 0; b < blockIdx.x; b++) pre += bsum[b];
    int excl = pre + (wid ? wsum[wid - 1] : 0) + ps - s;
    if (i < n4) {
        int4 o;
        o.x = excl;
        o.y = excl + v.x;
        o.z = excl + v.x + v.y;
        o.w = excl + v.x + v.y + v.z;
        reinterpret_cast<int4*>(offs)[i] = o;
    }
    if (blockIdx.x == gridDim.x - 1 && tid == 0)
        offs[n] = pre + bsum[blockIdx.x];
}

__global__ void fill_k(const int* __restrict__ key, const int* __restrict__ payload,
                       int n, int* __restrict__ cursor, int* __restrict__ list) {
    int i = blockIdx.x * blockDim.x + threadIdx.x;
    if (i >= n) return;
    int pos = atomicAdd(&cursor[key[i]], 1);
    list[pos] = payload[i];
}

// ---------------- warp-tiled half gathers (hadd2-tree inner loop) --------
__global__ __launch_bounds__(256) void gather256h_k(
    const __half* __restrict__ in, const int* __restrict__ offs,
    const int* __restrict__ list, int mode, const float* __restrict__ obias,
    __half* __restrict__ out, unsigned nrows)
{
    __shared__ int sidx[8][32];
    const int wslot = threadIdx.x >> 5;
    const int lane  = threadIdx.x & 31;
    unsigned r = blockIdx.x * 8u + wslot;
    if (r >= nrows) return;

    int s = offs[r], e = offs[r + 1];
    const uint4* in4 = reinterpret_cast<const uint4*>(in);
    float acc[8];
#pragma unroll
    for (int i = 0; i < 8; i++) acc[i] = 0.f;

    auto tree4 = [&](int n0, int n1, int n2, int n3) {
        uint4 v0 = in4[(size_t)n0 * 32 + lane];
        uint4 v1 = in4[(size_t)n1 * 32 + lane];
        uint4 v2 = in4[(size_t)n2 * 32 + lane];
        uint4 v3 = in4[(size_t)n3 * 32 + lane];
        const half2* h0 = reinterpret_cast<const half2*>(&v0);
        const half2* h1 = reinterpret_cast<const half2*>(&v1);
        const half2* h2 = reinterpret_cast<const half2*>(&v2);
        const half2* h3 = reinterpret_cast<const half2*>(&v3);
#pragma unroll
        for (int p = 0; p < 4; p++) {
            half2 t = __hadd2(__hadd2(h0[p], h1[p]), __hadd2(h2[p], h3[p]));
            float2 f = __half22float2(t);
            acc[2 * p] += f.x; acc[2 * p + 1] += f.y;
        }
    };
    auto one = [&](int nb) {
        uint4 v = in4[(size_t)nb * 32 + lane];
        const half2* h = reinterpret_cast<const half2*>(&v);
#pragma unroll
        for (int p = 0; p < 4; p++) {
            float2 f = __half22float2(h[p]);
            acc[2 * p] += f.x; acc[2 * p + 1] += f.y;
        }
    };

    int base = s;
    for (; base + 32 <= e; base += 32) {
        sidx[wslot][lane] = __ldg(&list[base + lane]);
        __syncwarp();
#pragma unroll
        for (int jj = 0; jj < 32; jj += 4)
            tree4(sidx[wslot][jj], sidx[wslot][jj + 1], sidx[wslot][jj + 2], sidx[wslot][jj + 3]);
        __syncwarp();
    }
    if (base < e) {
        int cnt = e - base;
        sidx[wslot][lane] = __ldg(&list[base + min(lane, cnt - 1)]);
        __syncwarp();
        int jj = 0;
        for (; jj + 4 <= cnt; jj += 4)
            tree4(sidx[wslot][jj], sidx[wslot][jj + 1], sidx[wslot][jj + 2], sidx[wslot][jj + 3]);
        for (; jj < cnt; jj++) one(sidx[wslot][jj]);
    }

    float deg = (float)(e - s);
    float sc = (mode == 0) ? (1.0f / fmaxf(deg, 1.0f)) : (deg > 0.f ? 1.0f / deg : 0.0f);
#pragma unroll
    for (int i = 0; i < 8; i++) acc[i] *= sc;
    if (obias) {
        const float4* b4 = reinterpret_cast<const float4*>(obias);
        float4 b0 = b4[lane * 2], b1 = b4[lane * 2 + 1];
        acc[0] = fmaxf(acc[0] + b0.x, 0.f); acc[1] = fmaxf(acc[1] + b0.y, 0.f);
        acc[2] = fmaxf(acc[2] + b0.z, 0.f); acc[3] = fmaxf(acc[3] + b0.w, 0.f);
        acc[4] = fmaxf(acc[4] + b1.x, 0.f); acc[5] = fmaxf(acc[5] + b1.y, 0.f);
        acc[6] = fmaxf(acc[6] + b1.z, 0.f); acc[7] = fmaxf(acc[7] + b1.w, 0.f);
    }
    uint4 o;
    half2* oh = reinterpret_cast<half2*>(&o);
#pragma unroll
    for (int p = 0; p < 4; p++) oh[p] = __floats2half2_rn(acc[2 * p], acc[2 * p + 1]);
    reinterpret_cast<uint4*>(out)[(size_t)r * 32 + lane] = o;
}

__global__ __launch_bounds__(256) void gather128h_k(
    const __half* __restrict__ in, const int* __restrict__ offs,
    const int* __restrict__ list, int mode,
    __half* __restrict__ out, unsigned nrows)
{
    __shared__ int sidx[8][32];
    const int wslot = threadIdx.x >> 5;
    const int lane  = threadIdx.x & 31;
    unsigned r = blockIdx.x * 8u + wslot;
    if (r >= nrows) return;

    int s = offs[r], e = offs[r + 1];
    const uint2* in2 = reinterpret_cast<const uint2*>(in);
    float acc[4] = {0.f, 0.f, 0.f, 0.f};

    auto tree4 = [&](int n0, int n1, int n2, int n3) {
        uint2 v0 = in2[(size_t)n0 * 32 + lane];
        uint2 v1 = in2[(size_t)n1 * 32 + lane];
        uint2 v2 = in2[(size_t)n2 * 32 + lane];
        uint2 v3 = in2[(size_t)n3 * 32 + lane];
        const half2* h0 = reinterpret_cast<const half2*>(&v0);
        const half2* h1 = reinterpret_cast<const half2*>(&v1);
        const half2* h2 = reinterpret_cast<const half2*>(&v2);
        const half2* h3 = reinterpret_cast<const half2*>(&v3);
#pragma unroll
        for (int p = 0; p < 2; p++) {
            half2 t = __hadd2(__hadd2(h0[p], h1[p]), __hadd2(h2[p], h3[p]));
            float2 f = __half22float2(t);
            acc[2 * p] += f.x; acc[2 * p + 1] += f.y;
        }
    };
    auto one = [&](int nb) {
        uint2 v = in2[(size_t)nb * 32 + lane];
        const half2* h = reinterpret_cast<const half2*>(&v);
        float2 f0 = __half22float2(h[0]), f1 = __half22float2(h[1]);
        acc[0] += f0.x; acc[1] += f0.y; acc[2] += f1.x; acc[3] += f1.y;
    };

    int base = s;
    for (; base + 32 <= e; base += 32) {
        sidx[wslot][lane] = __ldg(&list[base + lane]);
        __syncwarp();
#pragma unroll
        for (int jj = 0; jj < 32; jj += 4)
            tree4(sidx[wslot][jj], sidx[wslot][jj + 1], sidx[wslot][jj + 2], sidx[wslot][jj + 3]);
        __syncwarp();
    }
    if (base < e) {
        int cnt = e - base;
        sidx[wslot][lane] = __ldg(&list[base + min(lane, cnt - 1)]);
        __syncwarp();
        int jj = 0;
        for (; jj + 4 <= cnt; jj += 4)
            tree4(sidx[wslot][jj], sidx[wslot][jj + 1], sidx[wslot][jj + 2], sidx[wslot][jj + 3]);
        for (; jj < cnt; jj++) one(sidx[wslot][jj]);
    }

    float deg = (float)(e - s);
    float sc = (mode == 0) ? (1.0f / fmaxf(deg, 1.0f)) : (deg > 0.f ? 1.0f / deg : 0.0f);
    uint2 o;
    half2* oh = reinterpret_cast<half2*>(&o);
    oh[0] = __floats2half2_rn(acc[0] * sc, acc[1] * sc);
    oh[1] = __floats2half2_rn(acc[2] * sc, acc[3] * sc);
    reinterpret_cast<uint2*>(out)[(size_t)r * 32 + lane] = o;
}

// 40-wide half-in -> fp32-out, hadd2 pair tree. thread = (row, chunk of 8).
__global__ void gather40h_k(const __half* __restrict__ in, const int* __restrict__ offs,
                            const int* __restrict__ list, int mode,
                            float* __restrict__ out, unsigned nrows) {
    unsigned t = blockIdx.x * blockDim.x + threadIdx.x;
    if (t >= nrows * 5) return;
    unsigned r = t / 5;
    unsigned c = t - r * 5;
    int s = offs[r], e = offs[r + 1];
    const uint4* in4 = reinterpret_cast<const uint4*>(in);
    float acc[8];
#pragma unroll
    for (int i = 0; i < 8; i++) acc[i] = 0.f;
    int j = s;
    for (; j + 2 <= e; j += 2) {
        int n0 = __ldg(&list[j]), n1 = __ldg(&list[j + 1]);
        uint4 v0 = in4[(size_t)n0 * 5 + c];
        uint4 v1 = in4[(size_t)n1 * 5 + c];
        const half2* h0 = reinterpret_cast<const half2*>(&v0);
        const half2* h1 = reinterpret_cast<const half2*>(&v1);
#pragma unroll
        for (int p = 0; p < 4; p++) {
            float2 f = __half22float2(__hadd2(h0[p], h1[p]));
            acc[2 * p] += f.x; acc[2 * p + 1] += f.y;
        }
    }
    for (; j < e; j++) {
        int nb = __ldg(&list[j]);
        uint4 v = in4[(size_t)nb * 5 + c];
        const half2* h = reinterpret_cast<const half2*>(&v);
#pragma unroll
        for (int p = 0; p < 4; p++) {
            float2 f = __half22float2(h[p]);
            acc[2 * p] += f.x; acc[2 * p + 1] += f.y;
        }
    }
    float deg = (float)(e - s);
    float sc = (mode == 0) ? (1.0f / fmaxf(deg, 1.0f)) : (deg > 0.f ? 1.0f / deg : 0.0f);
    float4* o4 = reinterpret_cast<float4*>(out);
    o4[(size_t)r * 10 + c * 2 + 0] = make_float4(acc[0] * sc, acc[1] * sc, acc[2] * sc, acc[3] * sc);
    o4[(size_t)r * 10 + c * 2 + 1] = make_float4(acc[4] * sc, acc[5] * sc, acc[6] * sc, acc[7] * sc);
}

// 40-wide fp32-in -> fp32-out (runtime F4 = 10)
__global__ void gather_small_k(const float* __restrict__ in, const int* __restrict__ offs,
                               const int* __restrict__ list, int mode,
                               float* __restrict__ out, unsigned nrows, unsigned F4) {
    unsigned t = blockIdx.x * blockDim.x + threadIdx.x;
    if (t >= nrows * F4) return;
    unsigned r = t / F4;
    unsigned f4 = t - r * F4;
    int s = offs[r], e = offs[r + 1];
    const float4* in4 = reinterpret_cast<const float4*>(in);
    float4 acc = make_float4(0.f, 0.f, 0.f, 0.f);
    int j = s;
    for (; j + 4 <= e; j += 4) {
        int n0 = __ldg(&list[j]), n1 = __ldg(&list[j + 1]);
        int n2 = __ldg(&list[j + 2]), n3 = __ldg(&list[j + 3]);
        float4 v0 = in4[(size_t)n0 * F4 + f4];
        float4 v1 = in4[(size_t)n1 * F4 + f4];
        float4 v2 = in4[(size_t)n2 * F4 + f4];
        float4 v3 = in4[(size_t)n3 * F4 + f4];
        acc.x += v0.x + v1.x + v2.x + v3.x;
        acc.y += v0.y + v1.y + v2.y + v3.y;
        acc.z += v0.z + v1.z + v2.z + v3.z;
        acc.w += v0.w + v1.w + v2.w + v3.w;
    }
    for (; j < e; j++) {
        int nb = __ldg(&list[j]);
        float4 v = in4[(size_t)nb * F4 + f4];
        acc.x += v.x; acc.y += v.y; acc.z += v.z; acc.w += v.w;
    }
    float deg = (float)(e - s);
    float sc = (mode == 0) ? (1.0f / fmaxf(deg, 1.0f)) : (deg > 0.f ? 1.0f / deg : 0.0f);
    reinterpret_cast<float4*>(out)[t] = make_float4(acc.x * sc, acc.y * sc, acc.z * sc, acc.w * sc);
}

// ---------------- fp16 tensor-core dual GEMM (fp32 accumulate) ----------
#define BN 64
#define BKH 64
#define LDKH 72
#define CLD 36

template <int BMT>
__global__ __launch_bounds__(256, 2) void gemm_h_k(
    const __half* __restrict__ A1, const __half* __restrict__ W1,
    const __half* __restrict__ A2, const __half* __restrict__ W2,
    const float* __restrict__ addin, const float* __restrict__ bias,
    void* __restrict__ Cp, int Nr, int K, int O, int relu, int outHalf)
{
    constexpr int MI = BMT / 64;
    __shared__ union {
        struct {
            __half As[2][BMT][LDKH];
            __half Bs[2][BN][LDKH];
        } t;
        float Cs[8][16 * MI * CLD];
    } sm;

    const int bm   = blockIdx.y * BMT;
    const int bn   = blockIdx.x * BN;
    const int tid  = threadIdx.x;
    const int wid  = tid >> 5;
    const int lane = tid & 31;
    const int warpM = (wid >> 1) * (BMT / 4);
    const int warpN = (wid & 1) * 32;

    const int KT = K / BKH;
    const int npass = A2 ? 2 : 1;
    const int T = KT * npass;

    auto issue = [&](int t, int buf) {
        int p  = t / KT;
        int k0 = (t - p * KT) * BKH;
        const __half* A = p ? A2 : A1;
        const __half* W = p ? W2 : W1;
#pragma unroll
        for (int l = 0; l < BMT / 32; l++) {
            int e = tid + l * 256;
            int row = e >> 3, c8 = e & 7;
            int gm = min(bm + row, Nr - 1);
            const __half* src = A + (size_t)gm * K + k0 + c8 * 8;
            unsigned dst = (unsigned)__cvta_generic_to_shared(&sm.t.As[buf][row][c8 * 8]);
            asm volatile("cp.async.cg.shared.global [%0], [%1], 16;" :: "r"(dst), "l"(src));
        }
#pragma unroll
        for (int l = 0; l < 2; l++) {
            int e = tid + l * 256;
            int row = e >> 3, c8 = e & 7;
            int gn = min(bn + row, O - 1);
            const __half* src = W + (size_t)gn * K + k0 + c8 * 8;
            unsigned dst = (unsigned)__cvta_generic_to_shared(&sm.t.Bs[buf][row][c8 * 8]);
            asm volatile("cp.async.cg.shared.global [%0], [%1], 16;" :: "r"(dst), "l"(src));
        }
        asm volatile("cp.async.commit_group;");
    };

    wmma::fragment<wmma::accumulator, 16, 16, 16, float> acc[MI][2];
#pragma unroll
    for (int i = 0; i < MI; i++)
#pragma unroll
        for (int j = 0; j < 2; j++) wmma::fill_fragment(acc[i][j], 0.0f);

    issue(0, 0);
    for (int t = 0; t < T; t++) {
        int buf = t & 1;
        if (t + 1 < T) {
            issue(t + 1, buf ^ 1);
            asm volatile("cp.async.wait_group 1;");
        } else {
            asm volatile("cp.async.wait_group 0;");
        }
        __syncthreads();

#pragma unroll
        for (int kk = 0; kk < BKH; kk += 16) {
            wmma::fragment<wmma::matrix_a, 16, 16, 16, __half, wmma::row_major> af[MI];
            wmma::fragment<wmma::matrix_b, 16, 16, 16, __half, wmma::col_major> bf[2];
#pragma unroll
            for (int i = 0; i < MI; i++)
                wmma::load_matrix_sync(af[i], &sm.t.As[buf][warpM + i * 16][kk], LDKH);
#pragma unroll
            for (int j = 0; j < 2; j++)
                wmma::load_matrix_sync(bf[j], &sm.t.Bs[buf][warpN + j * 16][kk], LDKH);
#pragma unroll
            for (int i = 0; i < MI; i++)
#pragma unroll
                for (int j = 0; j < 2; j++)
                    wmma::mma_sync(acc[i][j], af[i], bf[j], acc[i][j]);
        }
        __syncthreads();
    }

#pragma unroll
    for (int i = 0; i < MI; i++)
#pragma unroll
        for (int j = 0; j < 2; j++)
            wmma::store_matrix_sync(&sm.Cs[wid][(i * 16) * CLD + j * 16], acc[i][j],
                                    CLD, wmma::mem_row_major);
    __syncwarp();

    for (int idx = lane; idx < 16 * MI * 32; idx += 32) {
        int r = idx >> 5;
        int c = idx & 31;
        int m = bm + warpM + r;
        int n = bn + warpN + c;
        if (m >= Nr || n >= O) continue;
        float v = sm.Cs[wid][r * CLD + c];
        if (addin) v += addin[(size_t)m * O + n];
        if (bias)  v += bias[n];
        if (relu)  v = fmaxf(v, 0.0f);
        if (outHalf) ((__half*)Cp)[(size_t)m * O + n] = __float2half_rn(v);
        else         ((float*)Cp)[(size_t)m * O + n] = v;
    }
}

// ---------------- final: logits + log_softmax (hb added to Hy) ----------------
__global__ void final_k(const float* __restrict__ S, const float* __restrict__ Hy,
                        const float* __restrict__ hb,
                        const float* __restrict__ lpw, const float* __restrict__ lpb,
                        float* __restrict__ out, int n) {
    __shared__ float w[CCLS * 2 * CCLS];
    __shared__ float bb[CCLS];
    __shared__ float hbb[CCLS];
    for (int i = threadIdx.x; i < CCLS * 2 * CCLS; i += blockDim.x) w[i] = lpw[i];
    for (int i = threadIdx.x; i < CCLS; i += blockDim.x) { bb[i] = lpb[i]; hbb[i] = hb[i]; }
    __syncthreads();
    int node = blockIdx.x * blockDim.x + threadIdx.x;
    if (node >= n) return;

    float sv[CCLS], hv[CCLS];
#pragma unroll
    for (int k = 0; k < CCLS; k++) {
        sv[k] = S [node * CCLS + k];
        hv[k] = Hy[node * CCLS + k] + hbb[k];
    }
    float logits[CCLS];
#pragma unroll 4
    for (int c = 0; c < CCLS; c++) {
        float acc = bb[c];
        const float* wr = &w[c * 2 * CCLS];
#pragma unroll
        for (int k = 0; k < CCLS; k++) acc += sv[k] * wr[k];
#pragma unroll
        for (int k = 0; k < CCLS; k++) acc += hv[k] * wr[CCLS + k];
        logits[c] = acc;
    }
    float mx = -1e30f;
#pragma unroll
    for (int c = 0; c < CCLS; c++) mx = fmaxf(mx, logits[c]);
    float sum = 0.0f;
#pragma unroll
    for (int c = 0; c < CCLS; c++) sum += __expf(logits[c] - mx);
    float lse = mx + logf(sum);
#pragma unroll
    for (int c = 0; c < CCLS; c++) out[node * CCLS + c] = logits[c] - lse;
}

// =======================================================================
extern "C" void kernel_launch(void* const* d_in, const int* in_sizes, int n_in,
                              void* d_out, int out_size) {
    const float* x       = (const float*)d_in[0];
    const int*   src     = (const int*)  d_in[1];
    const int*   dst     = (const int*)  d_in[2];
    const int*   he_node = (const int*)  d_in[3];
    const int*   he_edge = (const int*)  d_in[4];
    const float* s0wl = (const float*)d_in[5],  *s0wr = (const float*)d_in[6],  *s0b = (const float*)d_in[7];
    const float* s1wl = (const float*)d_in[8],  *s1wr = (const float*)d_in[9],  *s1b = (const float*)d_in[10];
    const float* s2wl = (const float*)d_in[11], *s2wr = (const float*)d_in[12], *s2b = (const float*)d_in[13];
    const float* h0w = (const float*)d_in[14], *h0b = (const float*)d_in[15];
    const float* h1w = (const float*)d_in[16], *h1b = (const float*)d_in[17];
    const float* h2w = (const float*)d_in[18], *h2b = (const float*)d_in[19];
    const float* h3w = (const float*)d_in[20], *h3b = (const float*)d_in[21];
    const float* h4w = (const float*)d_in[22], *h4b = (const float*)d_in[23];
    const float* lpw = (const float*)d_in[24], *lpb = (const float*)d_in[25];

    const int E   = in_sizes[1];
    const int ENH = in_sizes[3];
    const int FIN = in_sizes[0] / NN;   // 128

    __half *xh, *AGGh, *H1h, *H2h, *G1h, *G2h, *HXTh, *XT40h, *HXT40h, *EFh, *EF2h, *WH;
    float *AGG40, *EF40, *HYP40, *SIMPLE;
    cudaGetSymbolAddress((void**)&xh,     d_xh);
    cudaGetSymbolAddress((void**)&AGGh,   d_AGGh);
    cudaGetSymbolAddress((void**)&H1h,    d_H1h);
    cudaGetSymbolAddress((void**)&H2h,    d_H2h);
    cudaGetSymbolAddress((void**)&G1h,    d_G1h);
    cudaGetSymbolAddress((void**)&G2h,    d_G2h);
    cudaGetSymbolAddress((void**)&HXTh,   d_HXTh);
    cudaGetSymbolAddress((void**)&XT40h,  d_XT40h);
    cudaGetSymbolAddress((void**)&HXT40h, d_HXT40h);
    cudaGetSymbolAddress((void**)&EFh,    d_EFh);
    cudaGetSymbolAddress((void**)&EF2h,   d_EF2h);
    cudaGetSymbolAddress((void**)&WH,     d_WH);
    cudaGetSymbolAddress((void**)&AGG40,  d_AGG40);
    cudaGetSymbolAddress((void**)&EF40,   d_EF40);
    cudaGetSymbolAddress((void**)&HYP40,  d_HYP40);
    cudaGetSymbolAddress((void**)&SIMPLE, d_SIMPLE);

    int *dcnt, *doffs, *dcur, *dlist;
    int *necnt, *neoffs, *necur, *nelist;
    int *encnt, *enoffs, *encur, *enlist;
    int *bsumS, *bsumNE, *bsumEN;
    cudaGetSymbolAddress((void**)&dcnt,  d_dcnt);
    cudaGetSymbolAddress((void**)&doffs, d_doffs);
    cudaGetSymbolAddress((void**)&dcur,  d_dcur);
    cudaGetSymbolAddress((void**)&dlist, d_dlist);
    cudaGetSymbolAddress((void**)&necnt,  d_necnt);
    cudaGetSymbolAddress((void**)&neoffs, d_neoffs);
    cudaGetSymbolAddress((void**)&necur,  d_necur);
    cudaGetSymbolAddress((void**)&nelist, d_nelist);
    cudaGetSymbolAddress((void**)&encnt,  d_encnt);
    cudaGetSymbolAddress((void**)&enoffs, d_enoffs);
    cudaGetSymbolAddress((void**)&encur,  d_encur);
    cudaGetSymbolAddress((void**)&enlist, d_enlist);
    cudaGetSymbolAddress((void**)&bsumS,  d_bsumS);
    cudaGetSymbolAddress((void**)&bsumNE, d_bsumNE);
    cudaGetSymbolAddress((void**)&bsumEN, d_bsumEN);

    const int TB = 256;
    auto cdiv = [](int a, int b) { return (a + b - 1) / b; };
    dim3 gemm_blk(256);
    auto grid128 = [&](int Nr, int O) {
        return dim3((unsigned)cdiv(O, BN), (unsigned)cdiv(Nr, 128));
    };
    auto grid64 = [&](int Nr, int O) {
        return dim3((unsigned)cdiv(O, BN), (unsigned)cdiv(Nr, 64));
    };
    const int SB_NN = cdiv(NN / 4, 1024);
    const int SB_MM = cdiv(MM / 4, 1024);

    // -------- streams/events: created once, reused (R14 leak lesson) --------
    static cudaStream_t hs = nullptr, hs2 = nullptr;
    static cudaEvent_t evFork = nullptr, evJoin = nullptr, evEn = nullptr;
    if (!hs) {
        cudaStreamCreateWithFlags(&hs,  cudaStreamNonBlocking);
        cudaStreamCreateWithFlags(&hs2, cudaStreamNonBlocking);
        cudaEventCreateWithFlags(&evFork, cudaEventDisableTiming);
        cudaEventCreateWithFlags(&evJoin, cudaEventDisableTiming);
        cudaEventCreateWithFlags(&evEn,   cudaEventDisableTiming);
    }

    // ======== stream 0 prologue: xh conversion, then fork (R15 schedule) ===
    cvt1_k<<<cdiv(NN * FIN, TB), TB, 0, 0>>>(x, xh, NN * FIN);
    cudaEventRecord(evFork, 0);
    cudaStreamWaitEvent(hs,  evFork, 0);
    cudaStreamWaitEvent(hs2, evFork, 0);

    // ======== SAGE branch (stream 0) ========
    cudaMemsetAsync(dcnt, 0, NN * sizeof(int), 0);
    counti_k<<<cdiv(E, TB), TB, 0, 0>>>(dst, E, dcnt);
    scansum_k<<<SB_NN, 1024, 0, 0>>>(dcnt, bsumS, NN / 4);
    scanout_k<<<SB_NN, 1024, 0, 0>>>(dcnt, bsumS, doffs, NN);
    cudaMemcpyAsync(dcur, doffs, NN * sizeof(int), cudaMemcpyDeviceToDevice, 0);
    fill_k<<<cdiv(E, TB), TB, 0, 0>>>(dst, src, E, dcur, dlist);

    gather128h_k<<<cdiv(NN, 8), 256, 0, 0>>>(xh, doffs, dlist, 0, AGGh, NN);
    {
        Cvt6 b;
        b.s[0] = s0wl; b.d[0] = WH + WH_S0WL; b.n[0] = HIDW * FIN;
        b.s[1] = s0wr; b.d[1] = WH + WH_S0WR; b.n[1] = HIDW * FIN;
        b.s[2] = s1wl; b.d[2] = WH + WH_S1WL; b.n[2] = HIDW * HIDW;
        b.s[3] = s1wr; b.d[3] = WH + WH_S1WR; b.n[3] = HIDW * HIDW;
        b.s[4] = s2wl; b.d[4] = WH + WH_S2WL; b.n[4] = CCLS * HIDW;
        b.s[5] = s2wr; b.d[5] = WH + WH_S2WR; b.n[5] = CCLS * HIDW;
        cvtB_k<<<dim3(cdiv(HIDW * HIDW, TB), 6), TB, 0, 0>>>(b);
    }
    gemm_h_k<128><<<grid128(NN, HIDW), gemm_blk, 0, 0>>>(AGGh, WH + WH_S0WL, xh, WH + WH_S0WR,
                                                         nullptr, s0b, H1h, NN, FIN, HIDW, 1, 1);
    gather256h_k<<<cdiv(NN, 8), 256, 0, 0>>>(H1h, doffs, dlist, 0, nullptr, AGGh, NN);
    gemm_h_k<128><<<grid128(NN, HIDW), gemm_blk, 0, 0>>>(AGGh, WH + WH_S1WL, H1h, WH + WH_S1WR,
                                                         nullptr, s1b, H2h, NN, HIDW, HIDW, 1, 1);
    gemm_h_k<128><<<grid128(NN, CCLS), gemm_blk, 0, 0>>>(H2h, WH + WH_S2WL, nullptr, nullptr,
                                                         nullptr, nullptr, XT40h, NN, HIDW, CCLS, 0, 1);
    gather40h_k<<<cdiv(NN * 5, TB), TB, 0, 0>>>(XT40h, doffs, dlist, 0, AGG40, NN);
    gemm_h_k<128><<<grid128(NN, CCLS), gemm_blk, 0, 0>>>(H2h, WH + WH_S2WR, nullptr, nullptr,
                                                         AGG40, s2b, SIMPLE, NN, HIDW, CCLS, 0, 0);

    // ======== en-CSR build (stream hs2, overlaps ne-CSR + L0 on hs) ========
    cudaMemsetAsync(encnt, 0, NN * sizeof(int), hs2);
    counti_k<<<cdiv(ENH, TB), TB, 0, hs2>>>(he_node, ENH, encnt);
    scansum_k<<<SB_NN, 1024, 0, hs2>>>(encnt, bsumEN, NN / 4);
    scanout_k<<<SB_NN, 1024, 0, hs2>>>(encnt, bsumEN, enoffs, NN);
    cudaMemcpyAsync(encur, enoffs, NN * sizeof(int), cudaMemcpyDeviceToDevice, hs2);
    fill_k<<<cdiv(ENH, TB), TB, 0, hs2>>>(he_node, he_edge, ENH, encur, enlist);
    cudaEventRecord(evEn, hs2);

    // ======== Hypergraph branch (stream hs) ========
    {
        Cvt6 b;
        b.s[0] = h0w; b.d[0] = WH + WH_H0; b.n[0] = HIDW * FIN;
        b.s[1] = h1w; b.d[1] = WH + WH_H1; b.n[1] = HIDW * HIDW;
        b.s[2] = h2w; b.d[2] = WH + WH_H2; b.n[2] = HIDW * HIDW;
        b.s[3] = h3w; b.d[3] = WH + WH_H3; b.n[3] = HIDW * HIDW;
        b.s[4] = h4w; b.d[4] = WH + WH_H4; b.n[4] = CCLS * HIDW;
        b.s[5] = h4w; b.d[5] = WH + WH_H4; b.n[5] = 0;
        cvtB_k<<<dim3(cdiv(HIDW * HIDW, TB), 6), TB, 0, hs>>>(b);
    }
    cudaMemsetAsync(necnt, 0, MM * sizeof(int), hs);
    counti_k<<<cdiv(ENH, TB), TB, 0, hs>>>(he_edge, ENH, necnt);
    scansum_k<<<SB_MM, 1024, 0, hs>>>(necnt, bsumNE, MM / 4);
    scanout_k<<<SB_MM, 1024, 0, hs>>>(necnt, bsumNE, neoffs, MM);
    cudaMemcpyAsync(necur, neoffs, MM * sizeof(int), cudaMemcpyDeviceToDevice, hs);
    fill_k<<<cdiv(ENH, TB), TB, 0, hs>>>(he_edge, he_node, ENH, necur, nelist);

    gather128h_k<<<cdiv(MM, 8), 256, 0, hs>>>(xh, neoffs, nelist, 1, EFh, MM);
    cudaStreamWaitEvent(hs, evEn, 0);    // en-CSR ready (joins hs2 into hs)
    gather128h_k<<<cdiv(NN, 8), 256, 0, hs>>>(EFh, enoffs, enlist, 1, HXTh, NN);
    gemm_h_k<128><<<grid128(NN, HIDW), gemm_blk, 0, hs>>>(HXTh, WH + WH_H0, nullptr, nullptr,
                                                          nullptr, h0b, G1h, NN, FIN, HIDW, 1, 1);

    auto hyper_mid = [&](const __half* gin, const __half* w, const float* ob, __half* gout) {
        gather256h_k<<<cdiv(MM, 8), 256, 0, hs>>>(gin, neoffs, nelist, 1, nullptr, EFh, MM);
        gemm_h_k<64><<<grid64(MM, HIDW), gemm_blk, 0, hs>>>(EFh, w, nullptr, nullptr,
                                                            nullptr, nullptr, EF2h, MM, HIDW, HIDW, 0, 1);
        gather256h_k<<<cdiv(NN, 8), 256, 0, hs>>>(EF2h, enoffs, enlist, 1, ob, gout, NN);
    };
    hyper_mid(G1h, WH + WH_H1, h1b, G2h);
    hyper_mid(G2h, WH + WH_H2, h2b, G1h);
    hyper_mid(G1h, WH + WH_H3, h3b, G2h);

    gemm_h_k<128><<<grid128(NN, CCLS), gemm_blk, 0, hs>>>(G2h, WH + WH_H4, nullptr, nullptr,
                                                          nullptr, nullptr, HXT40h, NN, HIDW, CCLS, 0, 1);
    gather40h_k<<<cdiv(MM * 5, TB), TB, 0, hs>>>(HXT40h, neoffs, nelist, 1, EF40, MM);
    gather_small_k<<<cdiv(NN * 10, TB), TB, 0, hs>>>(EF40, enoffs, enlist, 1, HYP40, NN, 10);

    // -------- join + final --------
    cudaEventRecord(evJoin, hs);
    cudaStreamWaitEvent(0, evJoin, 0);
    final_k<<<cdiv(NN, 128), 128, 0, 0>>>(SIMPLE, HYP40, h4b, lpw, lpb, (float*)d_out, NN);
}